// round 7
// baseline (speedup 1.0000x reference)
#include <cuda_runtime.h>

// ---------------- problem constants ----------------
#define NV 16384
#define NC 8192
#define NE 65536
#define BB 1024
#define B4 256            // BB/4 float4 per row
#define CLIPV 15.0f
#define EPSF 1e-6f
#define ABS_MIN 6.1180464e-07f   // -log(tanh(15/2))

#define DV_REG 4          // reg-cached edges per variable
#define NTILE 4
#define TC4 (B4 / NTILE)  // 64 float4 columns per tile

// ---------------- scratch (static device globals) ----------------
__device__ int g_cntV[NV];
__device__ int g_rowV[NV + 1];
__device__ int g_curV[NV];
__device__ int g_edgeV[NE];
__device__ float g_amp[(size_t)NC * BB];       // 32 MB: row_sum(log tanh)
__device__ unsigned g_par[(size_t)NC * B4];    // 8 MB: packed parity bytes

// log(tanh(x/2)), x in [ABS_MIN, 15]  (always < 0)
__device__ __forceinline__ float logtanh_half(float x) {
    if (x > 0.5f) {
        float u = __expf(-x);                        // u <= 0.607
        return __logf(__fdividef(1.0f - u, 1.0f + u));
    } else {
        // log(x/2) - x^2/12 + 7*(x/2)^4/90  (abs err < 6e-6 on [0, 0.5])
        float z = 0.5f * x;
        float z2 = z * z;
        return __logf(z) + z2 * (-0.33333333f + z2 * 0.07777778f);
    }
}

__device__ __forceinline__ void red_add_v4(float* p, float4 v) {
    asm volatile("red.global.add.v4.f32 [%0], {%1, %2, %3, %4};"
                 :: "l"(p), "f"(v.x), "f"(v.y), "f"(v.z), "f"(v.w) : "memory");
}

__device__ __forceinline__ void red_xor_b32(unsigned* p, unsigned v) {
    asm volatile("red.global.xor.b32 [%0], %1;"
                 :: "l"(p), "r"(v) : "memory");
}

// ---------------- CSR build (variables only) ----------------
__global__ void __launch_bounds__(256) kCount(const int* __restrict__ vi)
{
    int e = blockIdx.x * 256 + threadIdx.x;
    if (e < NE) atomicAdd(&g_cntV[__ldg(vi + e)], 1);
}

__global__ void __launch_bounds__(1024) kScan()
{
    const int CH = NV / 1024;   // 16
    int t = threadIdx.x;
    int base = t * CH;
    int local[CH];
    int s = 0;
    for (int i = 0; i < CH; i++) { local[i] = s; s += g_cntV[base + i]; }
    __shared__ int sm[1024];
    sm[t] = s;
    __syncthreads();
    for (int d = 1; d < 1024; d <<= 1) {
        int x = (t >= d) ? sm[t - d] : 0;
        __syncthreads();
        sm[t] += x;
        __syncthreads();
    }
    int excl = (t == 0) ? 0 : sm[t - 1];
    for (int i = 0; i < CH; i++) {
        g_rowV[base + i] = excl + local[i];
        g_curV[base + i] = excl + local[i];
    }
    if (t == 1023) g_rowV[NV] = sm[1023];
}

__global__ void __launch_bounds__(256) kFill(const int* __restrict__ vi)
{
    int e = blockIdx.x * 256 + threadIdx.x;
    if (e < NE) {
        int p = atomicAdd(&g_curV[__ldg(vi + e)], 1);
        g_edgeV[p] = e;
    }
}

// ---------------- V step on one column tile ----------------
// block = (64, 4): 4 variables per block, 64 float4 cols
// also: outM init, check-row-sum RED accumulation (fused kHsum)
__global__ void __launch_bounds__(256) kV(
    const float4* __restrict__ chn, const float4* __restrict__ mc2v,
    const float4* __restrict__ mv2c,
    const int* __restrict__ ci,
    const float* __restrict__ Wi_p, const float* __restrict__ We_p,
    const float* __restrict__ gm_p,
    float4* __restrict__ outV2C, float4* __restrict__ outM, int col0)
{
    int v = blockIdx.x * 4 + threadIdx.y;
    int col = col0 + threadIdx.x;               // float4 column
    int s = __ldg(&g_rowV[v]), e1 = __ldg(&g_rowV[v + 1]);
    int deg = e1 - s;

    float Wi = __ldg(Wi_p), We = __ldg(We_p), g = __ldg(gm_p);
    float omg = 1.0f - g;
    float4 ch = __ldcs(chn + (size_t)v * B4 + col);

    // init marginal output
    outM[(size_t)v * B4 + col] =
        make_float4(Wi * ch.x, Wi * ch.y, Wi * ch.z, Wi * ch.w);
    if (deg == 0) return;

    float4 mreg[DV_REG];
    float sx = 0.f, sy = 0.f, sz = 0.f, sw = 0.f;
    #pragma unroll 4
    for (int j = 0; j < deg; j++) {
        int e = __ldg(&g_edgeV[s + j]);
        float4 m = __ldg(mc2v + (size_t)e * B4 + col);
        if (j < DV_REG) mreg[j] = m;
        sx += m.x; sy += m.y; sz += m.z; sw += m.w;
    }

    float ellx = Wi * ch.x, elly = Wi * ch.y, ellz = Wi * ch.z, ellw = Wi * ch.w;

    #pragma unroll 4
    for (int j = 0; j < deg; j++) {
        int e = __ldg(&g_edgeV[s + j]);
        float4 m = (j < DV_REG) ? mreg[j]
                                : __ldg(mc2v + (size_t)e * B4 + col); // L1 hit
        float4 mv = __ldcs(mv2c + (size_t)e * B4 + col);
        float o[4];
        o[0] = omg * mv.x + g * (ellx + We * (sx - m.x));
        o[1] = omg * mv.y + g * (elly + We * (sy - m.y));
        o[2] = omg * mv.z + g * (ellz + We * (sz - m.z));
        o[3] = omg * mv.w + g * (ellw + We * (sw - m.w));
        outV2C[(size_t)e * B4 + col] = make_float4(o[0], o[1], o[2], o[3]);

        // fused H row-sum accumulation
        int c = __ldg(ci + e);
        float lt[4];
        unsigned parpk = 0;
        #pragma unroll
        for (int i = 0; i < 4; i++) {
            float lm = fminf(fmaxf(o[i], -CLIPV), CLIPV);
            parpk |= ((lm < 0.f) ? 1u : 0u) << (8 * i);
            float al = fminf(fmaxf(fabsf(lm), ABS_MIN), CLIPV);
            lt[i] = logtanh_half(al);
        }
        red_add_v4(g_amp + (size_t)c * BB + col * 4,
                   make_float4(lt[0], lt[1], lt[2], lt[3]));
        if (parpk) red_xor_b32(&g_par[(size_t)c * B4 + col], parpk);
    }
}

// ---------------- H out: edge-centric streaming on one tile ----------------
// block = (64, 4): 4 edges per block
__global__ void __launch_bounds__(256) kHout(
    const float4* __restrict__ v2cNew, const float4* __restrict__ mc2v,
    const int* __restrict__ vi, const int* __restrict__ ci,
    const float* __restrict__ We_p, const float* __restrict__ gm_p,
    float4* __restrict__ outC2V, float* __restrict__ outM, int col0)
{
    int e = blockIdx.x * 4 + threadIdx.y;
    int col = col0 + threadIdx.x;
    int c = __ldg(ci + e);
    int v = __ldg(vi + e);

    float We = __ldg(We_p), g = __ldg(gm_p);
    float omg = 1.0f - g;

    float4 l4 = __ldg(v2cNew + (size_t)e * B4 + col);    // L2-warm from kV
    const float4* amp4 = reinterpret_cast<const float4*>(g_amp);
    float4 S4 = __ldg(amp4 + (size_t)c * B4 + col);
    unsigned p4 = __ldg(&g_par[(size_t)c * B4 + col]);
    float4 mc = __ldg(mc2v + (size_t)e * B4 + col);      // L2-warm from kV

    float lam[4] = {l4.x, l4.y, l4.z, l4.w};
    float Ss[4] = {S4.x, S4.y, S4.z, S4.w};
    float mcs[4] = {mc.x, mc.y, mc.z, mc.w};
    float os[4];

    #pragma unroll
    for (int i = 0; i < 4; i++) {
        float lm = fminf(fmaxf(lam[i], -CLIPV), CLIPV);
        unsigned ng = (lm < 0.f) ? 1u : 0u;
        float al = fminf(fmaxf(fabsf(lm), ABS_MIN), CLIPV);
        float lt = logtanh_half(al);
        float amp = fminf(Ss[i] - lt, 0.0f);
        unsigned par = ((p4 >> (8 * i)) & 1u) ^ ng;      // LOO parity
        float y = __expf(amp) * (1.0f - EPSF);
        float h = __logf(__fdividef(1.0f + y, 1.0f - y));  // 2*atanh(y) >= 0
        unsigned hu = __float_as_uint(h) ^ (par << 31);
        os[i] = omg * mcs[i] + g * __uint_as_float(hu);
    }

    float4 o = make_float4(os[0], os[1], os[2], os[3]);
    __stcs(outC2V + (size_t)e * B4 + col, o);

    float* dst = outM + (size_t)v * BB + col * 4;
    red_add_v4(dst, make_float4(We * o.x, We * o.y, We * o.z, We * o.w));
}

// ---------------- launch ----------------
extern "C" void kernel_launch(void* const* d_in, const int* in_sizes, int n_in,
                              void* d_out, int out_size)
{
    (void)in_sizes; (void)n_in; (void)out_size;

    const float* chn  = (const float*)d_in[0];
    const float* mc2v = (const float*)d_in[1];
    const float* mv2c = (const float*)d_in[2];
    const float* Wi   = (const float*)d_in[3];
    const float* We   = (const float*)d_in[4];
    const float* gm   = (const float*)d_in[5];
    const int*   vi   = (const int*)d_in[6];
    const int*   ci   = (const int*)d_in[7];

    // outputs: (msg_C2V, msg_V2C, output)
    float* outC2V = (float*)d_out;
    float* outV2C = outC2V + (size_t)NE * BB;
    float* outM   = outV2C + (size_t)NE * BB;

    void *pcv, *pamp, *ppar;
    cudaGetSymbolAddress(&pcv, g_cntV);
    cudaGetSymbolAddress(&pamp, g_amp);
    cudaGetSymbolAddress(&ppar, g_par);
    cudaMemsetAsync(pcv, 0, sizeof(int) * NV, 0);
    cudaMemsetAsync(pamp, 0, sizeof(float) * (size_t)NC * BB, 0);
    cudaMemsetAsync(ppar, 0, sizeof(unsigned) * (size_t)NC * B4, 0);

    kCount<<<NE / 256, 256>>>(vi);
    kScan<<<1, 1024>>>();
    kFill<<<NE / 256, 256>>>(vi);

    dim3 blk(TC4, 4);
    for (int t = 0; t < NTILE; t++) {
        int col0 = t * TC4;
        kV<<<NV / 4, blk>>>((const float4*)chn, (const float4*)mc2v,
                            (const float4*)mv2c, ci, Wi, We, gm,
                            (float4*)outV2C, (float4*)outM, col0);
        kHout<<<NE / 4, blk>>>((const float4*)outV2C, (const float4*)mc2v,
                               vi, ci, We, gm, (float4*)outC2V, outM, col0);
    }
}